// round 5
// baseline (speedup 1.0000x reference)
#include <cuda_runtime.h>
#include <cstdint>

#define NPAP 4096
#define NAUT 2048
#define HD   128
#define CANDMAX 1024

// ---------------- threefry2x32 (JAX, 20 rounds) ----------------
__host__ __device__ __forceinline__ void tf2x32(unsigned k0, unsigned k1,
                                                unsigned x0, unsigned x1,
                                                unsigned &o0, unsigned &o1) {
  unsigned ks2 = k0 ^ k1 ^ 0x1BD11BDAu;
  x0 += k0; x1 += k1;
#define TFR(r) { x0 += x1; x1 = (x1 << (r)) | (x1 >> (32 - (r))); x1 ^= x0; }
  TFR(13) TFR(15) TFR(26) TFR(6)  x0 += k1;  x1 += ks2 + 1u;
  TFR(17) TFR(29) TFR(16) TFR(24) x0 += ks2; x1 += k0 + 2u;
  TFR(13) TFR(15) TFR(26) TFR(6)  x0 += k0;  x1 += k1 + 3u;
  TFR(17) TFR(29) TFR(16) TFR(24) x0 += k1;  x1 += ks2 + 4u;
  TFR(13) TFR(15) TFR(26) TFR(6)  x0 += ks2; x1 += k0 + 5u;
#undef TFR
  o0 = x0; o1 = x1;
}
__device__ __forceinline__ unsigned jax_bits(unsigned k0, unsigned k1, unsigned m) {
  unsigned o0, o1; tf2x32(k0, k1, 0u, m, o0, o1); return o0 ^ o1;
}

// ---------------- scratch arena ----------------
__device__ __align__(256) unsigned char g_arena[32u * 1024u * 1024u];

// ---------------- CSR build (fused, x4 vectorized) ----------------
struct EdgeJobs {
  const int* key[6]; const int* part[6];
  const int* off[6]; int* cnt[6]; int* cur[6]; int* out[6];
  int pack[6];
  int eStart[7];
};
__global__ void count_all(EdgeJobs ej, int total) {
  int g4 = (blockIdx.x * blockDim.x + threadIdx.x) * 4;
  if (g4 >= total) return;
  int r = 0;
  while (g4 >= ej.eStart[r + 1]) r++;
  int e = g4 - ej.eStart[r];
  int4 k = *(const int4*)(ej.key[r] + e);
  atomicAdd(&ej.cnt[r][k.x], 1);
  atomicAdd(&ej.cnt[r][k.y], 1);
  atomicAdd(&ej.cnt[r][k.z], 1);
  atomicAdd(&ej.cnt[r][k.w], 1);
}
__global__ void fill_all(EdgeJobs ej, int total) {
  int g4 = (blockIdx.x * blockDim.x + threadIdx.x) * 4;
  if (g4 >= total) return;
  int r = 0;
  while (g4 >= ej.eStart[r + 1]) r++;
  int e = g4 - ej.eStart[r];
  int4 k = *(const int4*)(ej.key[r] + e);
  int4 p = *(const int4*)(ej.part[r] + e);
  int pk = ej.pack[r];
  const int* off = ej.off[r];
  int* cur = ej.cur[r];
  int* out = ej.out[r];
#define DOF(K, P, EE) { int pos = atomicAdd(&cur[K], 1); \
    out[off[K] + pos] = (P) | (pk ? ((EE) << 12) : 0); }
  DOF(k.x, p.x, e)
  DOF(k.y, p.y, e + 1)
  DOF(k.z, p.z, e + 2)
  DOF(k.w, p.w, e + 3)
#undef DOF
}
struct ScanArgs { const int* cnt[6]; int* off[6]; int n[6]; };
__global__ void scan_kernel(ScanArgs a) {
  int b = blockIdx.x;
  const int* cnt = a.cnt[b]; int* off = a.off[b]; int n = a.n[b];
  __shared__ int part[256];
  int t = threadIdx.x, chunk = (n + 255) / 256, st = t * chunk, s = 0;
  for (int j = 0; j < chunk; j++) { int i = st + j; if (i < n) s += cnt[i]; }
  part[t] = s; __syncthreads();
  for (int d = 1; d < 256; d <<= 1) {
    int v = (t >= d) ? part[t - d] : 0;
    __syncthreads(); part[t] += v; __syncthreads();
  }
  int run = (t == 0) ? 0 : part[t - 1];
  for (int j = 0; j < chunk; j++) {
    int i = st + j;
    if (i < n) { off[i] = run; run += cnt[i]; }
  }
  if (t == 255) off[n] = part[255];
}

// ---------------- multi-job mean gather ----------------
struct GJob { const int* off; const int* part; const float* H; float* out;
              const int* sel; int n; };
struct GJobs { GJob j[4]; };
__global__ __launch_bounds__(256) void gather_all(GJobs gj) {
  GJob jb = gj.j[blockIdx.y];
  int node = blockIdx.x * 8 + (threadIdx.x >> 5);
  if (node >= jb.n) return;
  int lane = threadIdx.x & 31;
  int b = jb.off[node], e = jb.off[node + 1];
  float4 acc = make_float4(0.f, 0.f, 0.f, 0.f);
  if (jb.sel) {
    for (int q = b; q < e; ++q) {
      int s = jb.part[q];
      const int* sp = &jb.sel[s * 5];
      if (sp[0] == node || sp[1] == node || sp[2] == node || sp[3] == node ||
          sp[4] == node) {
        float4 v = *((const float4*)(jb.H + (size_t)s * HD) + lane);
        acc.x += v.x; acc.y += v.y; acc.z += v.z; acc.w += v.w;
      }
    }
  } else {
    int q = b;
    for (; q + 4 <= e; q += 4) {
      int s0 = jb.part[q], s1 = jb.part[q + 1];
      int s2 = jb.part[q + 2], s3 = jb.part[q + 3];
      float4 v0 = *((const float4*)(jb.H + (size_t)s0 * HD) + lane);
      float4 v1 = *((const float4*)(jb.H + (size_t)s1 * HD) + lane);
      float4 v2 = *((const float4*)(jb.H + (size_t)s2 * HD) + lane);
      float4 v3 = *((const float4*)(jb.H + (size_t)s3 * HD) + lane);
      acc.x += (v0.x + v1.x) + (v2.x + v3.x);
      acc.y += (v0.y + v1.y) + (v2.y + v3.y);
      acc.z += (v0.z + v1.z) + (v2.z + v3.z);
      acc.w += (v0.w + v1.w) + (v2.w + v3.w);
    }
    for (; q < e; ++q) {
      int s = jb.part[q];
      float4 v = *((const float4*)(jb.H + (size_t)s * HD) + lane);
      acc.x += v.x; acc.y += v.y; acc.z += v.z; acc.w += v.w;
    }
  }
  float inv = 1.f / fmaxf((float)(e - b), 1.f);
  acc.x *= inv; acc.y *= inv; acc.z *= inv; acc.w *= inv;
  *((float4*)(jb.out + (size_t)node * HD) + lane) = acc;
}

// ------------- multi-job multi-pair GEMM, f32x2, K=128, 32x128 tile -------------
struct GemmJob { const float* A[3]; const float* B[3]; float* C;
                 int M, N, npairs, relu, rbStart; };   // rbStart in 32-row units
struct GemmJobs { GemmJob j[4]; int njobs; };
__global__ __launch_bounds__(256) void gemm_all(GemmJobs gjs) {
  int by = blockIdx.y;
  int ji = 0;
  while (ji + 1 < gjs.njobs && by >= gjs.j[ji + 1].rbStart) ji++;
  GemmJob jb = gjs.j[ji];
  int row0 = (by - jb.rbStart) * 32;
  int col0 = blockIdx.x * 128;
  if (col0 >= jb.N) return;
  __shared__ float As[16][36];
  __shared__ float Bs[16][132];
  unsigned long long acc[2][4];
#pragma unroll
  for (int i = 0; i < 2; i++)
#pragma unroll
    for (int j = 0; j < 4; j++) acc[i][j] = 0ull;
  int tid = threadIdx.x;
  int tyr = tid >> 4, tx = tid & 15;
  for (int p = 0; p < jb.npairs; p++) {
    const float* A = jb.A[p];
    const float* B = jb.B[p];
    for (int kt = 0; kt < 128; kt += 16) {
      {
        int m = tid >> 3, kk = (tid & 7) * 2;
        float2 v = *(const float2*)(A + (size_t)(row0 + m) * 128 + kt + kk);
        As[kk][m] = v.x; As[kk + 1][m] = v.y;
      }
#pragma unroll
      for (int q = 0; q < 2; q++) {
        int li = tid * 2 + q;
        int kk = li >> 5;
        int n4 = (li & 31) * 4;
        float4 v = *(const float4*)(B + (size_t)(kt + kk) * jb.N + col0 + n4);
        Bs[kk][n4] = v.x; Bs[kk][n4 + 1] = v.y; Bs[kk][n4 + 2] = v.z; Bs[kk][n4 + 3] = v.w;
      }
      __syncthreads();
#pragma unroll
      for (int k = 0; k < 16; k++) {
        unsigned long long a2[2], b2[4];
#pragma unroll
        for (int i = 0; i < 2; i++) {
          unsigned ai = __float_as_uint(As[k][tyr * 2 + i]);
          asm("mov.b64 %0, {%1, %1};" : "=l"(a2[i]) : "r"(ai));
        }
#pragma unroll
        for (int j = 0; j < 4; j++)
          b2[j] = *(const unsigned long long*)&Bs[k][tx * 8 + j * 2];
#pragma unroll
        for (int i = 0; i < 2; i++)
#pragma unroll
          for (int j = 0; j < 4; j++)
            asm("fma.rn.f32x2 %0, %1, %2, %0;" : "+l"(acc[i][j])
                : "l"(a2[i]), "l"(b2[j]));
      }
      __syncthreads();
    }
  }
#pragma unroll
  for (int i = 0; i < 2; i++) {
    int row = row0 + tyr * 2 + i;
#pragma unroll
    for (int j = 0; j < 4; j++) {
      unsigned u0, u1;
      asm("mov.b64 {%0, %1}, %2;" : "=r"(u0), "=r"(u1) : "l"(acc[i][j]));
      float c0 = __uint_as_float(u0), c1 = __uint_as_float(u1);
      if (jb.relu) { c0 = fmaxf(c0, 0.f); c1 = fmaxf(c1, 0.f); }
      float2* cp = (float2*)(jb.C + (size_t)row * jb.N + col0 + tx * 8 + j * 2);
      *cp = make_float2(c0, c1);
    }
  }
}

// ------------- prune: edge MLP + coalesce + compact gumbel top-5 + w out -------------
__device__ __forceinline__ unsigned long long packkey(float v, int j) {
  unsigned u = __float_as_uint(v);
  u = (u >> 31) ? ~u : (u | 0x80000000u);
  return (((unsigned long long)u) << 32) |
         (unsigned long long)(0xFFFFFFFFu - (unsigned)j);
}
struct PruneCfg {
  const int* roff; const int* rpart;
  const float* U; const float* V;
  const float* b1; const float* W2; const float* b2;
  int Nc; unsigned k0, k1; int* sel; float* outW;
};
__global__ __launch_bounds__(256) void prune_all(PruneCfg cp, PruneCfg ca, int nPP) {
  PruneCfg cfg = (blockIdx.x < nPP) ? cp : ca;
  int i = (blockIdx.x < nPP) ? blockIdx.x : blockIdx.x - nPP;
  extern __shared__ float sm[];
  float* Arow = sm;                           // Nc
  float* Urow = sm + cfg.Nc;                  // 256
  float* W2c  = Urow + 256;                   // 256
  unsigned long long* cand = (unsigned long long*)(W2c + 256);  // CANDMAX
  __shared__ unsigned long long red[8];
  __shared__ int sel5[5];
  __shared__ int ncand;
  int t = threadIdx.x, warp = t >> 5, lane = t & 31;
  if (t == 0) ncand = 0;
  Urow[t] = cfg.U[(size_t)i * 256 + t] + cfg.b1[t];
  W2c[t] = cfg.W2[2 * t];
  for (int j = t; j < cfg.Nc; j += 256) Arow[j] = 0.f;
  __syncthreads();

  int b = cfg.roff[i], nE = cfg.roff[i + 1] - b;
  float b2v = cfg.b2[0];
  const float4* U4 = (const float4*)&Urow[lane * 8];
  const float4* W4 = (const float4*)&W2c[lane * 8];
  float4 u0 = U4[0], u1 = U4[1], w0 = W4[0], w1 = W4[1];
  for (int e = warp; e < nE; e += 8) {
    int p = cfg.rpart[b + e];
    int d = p & 4095;
    const float4* V4 = (const float4*)(cfg.V + (size_t)d * 256) + lane * 2;
    float4 v0 = V4[0], v1 = V4[1];
    float acc = fmaxf(u0.x + v0.x, 0.f) * w0.x + fmaxf(u0.y + v0.y, 0.f) * w0.y +
                fmaxf(u0.z + v0.z, 0.f) * w0.z + fmaxf(u0.w + v0.w, 0.f) * w0.w +
                fmaxf(u1.x + v1.x, 0.f) * w1.x + fmaxf(u1.y + v1.y, 0.f) * w1.y +
                fmaxf(u1.z + v1.z, 0.f) * w1.z + fmaxf(u1.w + v1.w, 0.f) * w1.w;
#pragma unroll
    for (int o = 16; o; o >>= 1) acc += __shfl_xor_sync(0xffffffffu, acc, o);
    if (lane == 0) atomicAdd(&Arow[d], acc + b2v);
  }
  __syncthreads();

  for (int j = t; j < cfg.Nc; j += 256) {
    float a = Arow[j];
    if (a > 0.f) {
      unsigned m = (unsigned)i * (unsigned)cfg.Nc + (unsigned)j;
      unsigned bits = jax_bits(cfg.k0, cfg.k1, m);
      float f = __uint_as_float((bits >> 9) | 0x3f800000u) - 1.0f;
      float u = fmaxf(1e-10f, f + 1e-10f);
      float y = a + (-logf(-logf(u)));
      int pos = atomicAdd(&ncand, 1);
      if (pos < CANDMAX) cand[pos] = packkey(y, j);
    }
  }
  __syncthreads();
  int nc = ncand < CANDMAX ? ncand : CANDMAX;

  unsigned long long prev = 0;
  for (int r = 0; r < 5; r++) {
    unsigned long long best = 0ull;
    for (int q = t; q < nc; q += 256) {
      unsigned long long k = cand[q];
      if (k == prev) { cand[q] = 0ull; k = 0ull; }
      if (k > best) best = k;
    }
#pragma unroll
    for (int o = 16; o; o >>= 1) {
      unsigned long long v = __shfl_xor_sync(0xffffffffu, best, o);
      if (v > best) best = v;
    }
    if (lane == 0) red[warp] = best;
    __syncthreads();
    if (t == 0) {
      unsigned long long w = red[0];
      for (int q = 1; q < 8; q++) if (red[q] > w) w = red[q];
      red[0] = w;
      sel5[r] = (w != 0ull) ? (int)(0xFFFFFFFFu - (unsigned)(w & 0xFFFFFFFFull)) : -1;
    }
    __syncthreads();
    prev = red[0];
    __syncthreads();
  }
  if (t == 0) {
    int r = 0;
    while (r < 5 && sel5[r] >= 0) r++;
    for (int j = 0; j < cfg.Nc && r < 5; j++)
      if (!(Arow[j] > 0.f)) sel5[r++] = j;
    for (int q = 0; q < 5; q++) cfg.sel[i * 5 + q] = sel5[q];
  }
  __syncthreads();

  int s0 = sel5[0], s1 = sel5[1], s2 = sel5[2], s3 = sel5[3], s4 = sel5[4];
  for (int e = t; e < nE; e += 256) {
    int p = cfg.rpart[b + e];
    int d = p & 4095;
    int eid = p >> 12;
    cfg.outW[eid] = (d == s0 || d == s1 || d == s2 || d == s3 || d == s4) ? 1.f : 0.f;
  }
}

// ---------------- GNN2 layer1 for node `index` + classifier ----------------
__global__ __launch_bounds__(128) void node_out_kernel(
    const int* __restrict__ idxPtr,
    const float* __restrict__ HP0, const float* __restrict__ HA0,
    const int* __restrict__ ppoff, const int* __restrict__ pppart,
    const int* __restrict__ selpp,
    const int* __restrict__ apoff, const int* __restrict__ appart,
    const float* __restrict__ Wself, const float* __restrict__ Wpp1,
    const float* __restrict__ Wap1,
    const float* __restrict__ Wc, const float* __restrict__ bc,
    float* __restrict__ out) {
  __shared__ float selfv[128], mpp[128], mapv[128], agg[128];
  int t = threadIdx.x;
  int idx = idxPtr[0];
  selfv[t] = HP0[(size_t)idx * HD + t];
  int b = ppoff[idx], e = ppoff[idx + 1];
  float s = 0.f;
  for (int q = b; q < e; q++) {
    int sn = pppart[q];
    const int* sp = &selpp[sn * 5];
    if (sp[0] == idx || sp[1] == idx || sp[2] == idx || sp[3] == idx || sp[4] == idx)
      s += HP0[(size_t)sn * HD + t];
  }
  mpp[t] = s / fmaxf((float)(e - b), 1.f);
  b = apoff[idx]; e = apoff[idx + 1];
  s = 0.f;
  for (int q = b; q < e; q++) s += HA0[(size_t)appart[q] * HD + t];
  mapv[t] = s / fmaxf((float)(e - b), 1.f);
  __syncthreads();
  float a = 0.f;
  for (int k = 0; k < HD; k++)
    a += selfv[k] * Wself[k * HD + t] + mpp[k] * Wpp1[k * HD + t] +
         mapv[k] * Wap1[k * HD + t];
  agg[t] = fmaxf(a, 0.f);
  __syncthreads();
  if (t < 5) {
    float y = bc[t];
    for (int k = 0; k < HD; k++) y += agg[k] * Wc[k * 5 + t];
    out[t] = y;
  }
}

// ---------------- host launcher ----------------
extern "C" void kernel_launch(void* const* d_in, const int* in_sizes, int n_in,
                              void* d_out, int out_size) {
  const float* x_p = (const float*)d_in[0];
  const float* x_a = (const float*)d_in[1];
  const int* ei_pp = (const int*)d_in[2];
  const int* ei_aa = (const int*)d_in[3];
  const int* ei_pa = (const int*)d_in[4];
  const int* ei_ap = (const int*)d_in[5];
  const int* idxPtr = (const int*)d_in[8];
  const float* Ws_p0 = (const float*)d_in[9];
  const float* Ws_p1 = (const float*)d_in[10];
  const float* Ws_a0 = (const float*)d_in[11];
  const float* Ws_a1 = (const float*)d_in[12];
  const float* Wpp0 = (const float*)d_in[13];
  const float* Wpp1 = (const float*)d_in[14];
  const float* Waa0 = (const float*)d_in[15];
  const float* Waa1 = (const float*)d_in[16];
  const float* Wpa0 = (const float*)d_in[17];
  const float* Wap0 = (const float*)d_in[19];
  const float* Wap1 = (const float*)d_in[20];
  const float* Wep1_pp = (const float*)d_in[21];
  const float* bep1_pp = (const float*)d_in[22];
  const float* Wep2_pp = (const float*)d_in[23];
  const float* bep2_pp = (const float*)d_in[24];
  const float* Wep1_aa = (const float*)d_in[25];
  const float* bep1_aa = (const float*)d_in[26];
  const float* Wep2_aa = (const float*)d_in[27];
  const float* bep2_aa = (const float*)d_in[28];
  const float* Wc = (const float*)d_in[29];
  const float* bc = (const float*)d_in[30];

  int Epp = in_sizes[2] / 2, Eaa = in_sizes[3] / 2;
  int Epa = in_sizes[4] / 2, Eap = in_sizes[5] / 2;
  const int* pp_src = ei_pp;  const int* pp_dst = ei_pp + Epp;
  const int* aa_src = ei_aa;  const int* aa_dst = ei_aa + Eaa;
  const int* pa_src = ei_pa;  const int* pa_dst = ei_pa + Epa;
  const int* ap_src = ei_ap;  const int* ap_dst = ei_ap + Eap;

  unsigned kpp0, kpp1, kaa0, kaa1;
  tf2x32(0u, 42u, 0u, 0u, kpp0, kpp1);
  tf2x32(0u, 42u, 0u, 1u, kaa0, kaa1);

  static cudaStream_t s1 = nullptr;
  static cudaEvent_t e0 = nullptr, e1 = nullptr;
  if (!s1) {
    cudaStreamCreateWithFlags(&s1, cudaStreamNonBlocking);
    cudaEventCreateWithFlags(&e0, cudaEventDisableTiming);
    cudaEventCreateWithFlags(&e1, cudaEventDisableTiming);
  }

  void* basep = nullptr;
  cudaGetSymbolAddress(&basep, g_arena);
  unsigned char* ar = (unsigned char*)basep;
  size_t off = 0;
  auto carve = [&](size_t bytes) -> unsigned char* {
    unsigned char* p = ar + off;
    off += (bytes + 255) & ~(size_t)255;
    return p;
  };
  float* AGGP  = (float*)carve((size_t)NPAP * HD * 4);
  float* AGGA  = (float*)carve((size_t)NAUT * HD * 4);
  float* AGGP2 = (float*)carve((size_t)NPAP * HD * 4);
  float* AGGA2 = (float*)carve((size_t)NAUT * HD * 4);
  float* HP0 = (float*)carve((size_t)NPAP * HD * 4);
  float* HP1 = (float*)carve((size_t)NPAP * HD * 4);
  float* HA0 = (float*)carve((size_t)NAUT * HD * 4);
  float* HA1 = (float*)carve((size_t)NAUT * HD * 4);
  float* UP = (float*)carve((size_t)NPAP * 256 * 4);
  float* VP = (float*)carve((size_t)NPAP * 256 * 4);
  float* UA = (float*)carve((size_t)NAUT * 256 * 4);
  float* VA = (float*)carve((size_t)NAUT * 256 * 4);
  int* CNT = (int*)carve(6 * 4096 * 4);
  int* CUR = (int*)carve(6 * 4096 * 4);
  int* OFF = (int*)carve(6 * 4097 * 4);
  int* P0 = (int*)carve((size_t)Epp * 4);   // pp dst-CSR: partner=src
  int* P1 = (int*)carve((size_t)Epp * 4);   // pp src-CSR: packed dst|eid<<12
  int* P2 = (int*)carve((size_t)Eaa * 4);   // aa dst-CSR
  int* P3 = (int*)carve((size_t)Eaa * 4);   // aa src-CSR: packed
  int* P4 = (int*)carve((size_t)Epa * 4);   // pa dst-CSR
  int* P5 = (int*)carve((size_t)Eap * 4);   // ap dst-CSR
  int* SELPP = (int*)carve((size_t)NPAP * 5 * 4);
  int* SELAA = (int*)carve((size_t)NAUT * 5 * 4);

  const int* keys[6]  = {pp_dst, pp_src, aa_dst, aa_src, pa_dst, ap_dst};
  const int* parts[6] = {pp_src, pp_dst, aa_src, aa_dst, pa_src, ap_src};
  int ns[6] = {NPAP, NPAP, NAUT, NAUT, NAUT, NPAP};
  int Es[6] = {Epp, Epp, Eaa, Eaa, Epa, Eap};
  int packs[6] = {0, 1, 0, 1, 0, 0};
  int* outs[6] = {P0, P1, P2, P3, P4, P5};

  // ---- zero counters (both branches) then fork ----
  cudaMemsetAsync(CNT, 0, 2 * 6 * 4096 * 4);   // CNT+CUR contiguous
  cudaEventRecord(e0, 0);
  cudaStreamWaitEvent(s1, e0, 0);

  // ---- main-branch CSRs (pp, aa; rel 0..3) ----
  {
    EdgeJobs ej; int run = 0;
    for (int r = 0; r < 4; r++) {
      ej.key[r] = keys[r]; ej.part[r] = parts[r];
      ej.off[r] = OFF + r * 4097;
      ej.cnt[r] = CNT + r * 4096; ej.cur[r] = CUR + r * 4096;
      ej.out[r] = outs[r]; ej.pack[r] = packs[r];
      ej.eStart[r] = run; run += Es[r];
    }
    for (int r = 4; r <= 6; r++) ej.eStart[r] = run;
    count_all<<<(run / 4 + 255) / 256, 256>>>(ej, run);
    ScanArgs sa;
    for (int r = 0; r < 4; r++) {
      sa.cnt[r] = CNT + r * 4096; sa.off[r] = OFF + r * 4097; sa.n[r] = ns[r];
    }
    scan_kernel<<<4, 256>>>(sa);
    fill_all<<<(run / 4 + 255) / 256, 256>>>(ej, run);
  }
  // ---- side-branch CSRs (pa, ap; rel 4,5) + their x-gathers, on s1 ----
  {
    EdgeJobs ej; int run = 0;
    for (int r = 0; r < 2; r++) {
      int rr = r + 4;
      ej.key[r] = keys[rr]; ej.part[r] = parts[rr];
      ej.off[r] = OFF + rr * 4097;
      ej.cnt[r] = CNT + rr * 4096; ej.cur[r] = CUR + rr * 4096;
      ej.out[r] = outs[rr]; ej.pack[r] = packs[rr];
      ej.eStart[r] = run; run += Es[rr];
    }
    for (int r = 2; r <= 6; r++) ej.eStart[r] = run;
    count_all<<<(run / 4 + 255) / 256, 256, 0, s1>>>(ej, run);
    ScanArgs sa;
    for (int r = 0; r < 2; r++) {
      int rr = r + 4;
      sa.cnt[r] = CNT + rr * 4096; sa.off[r] = OFF + rr * 4097; sa.n[r] = ns[rr];
    }
    scan_kernel<<<2, 256, 0, s1>>>(sa);
    fill_all<<<(run / 4 + 255) / 256, 256, 0, s1>>>(ej, run);
    GJobs gj;
    gj.j[0] = {OFF + 5 * 4097, P5, x_a, AGGP2, nullptr, NPAP};
    gj.j[1] = {OFF + 4 * 4097, P4, x_p, AGGA2, nullptr, NAUT};
    gather_all<<<dim3((NPAP + 7) / 8, 2), 256, 0, s1>>>(gj);
    cudaEventRecord(e1, s1);
  }

  auto makeG = [&](int csr, const float* H, float* o, const int* sel, int n) {
    GJob j; j.off = OFF + csr * 4097; j.part = outs[csr]; j.H = H; j.out = o;
    j.sel = sel; j.n = n; return j;
  };

  // ---- GNN1 ----
  {
    GJobs gj; gj.j[0] = makeG(0, x_p, AGGP, nullptr, NPAP);
    gj.j[1] = makeG(2, x_a, AGGA, nullptr, NAUT);
    gather_all<<<dim3((NPAP + 7) / 8, 2), 256>>>(gj);
  }
  {
    GemmJobs gs; gs.njobs = 2;
    gs.j[0] = {{x_p, AGGP, nullptr}, {Ws_p0, Wpp0, nullptr}, HP0, NPAP, 128, 2, 1, 0};
    gs.j[1] = {{x_a, AGGA, nullptr}, {Ws_a0, Waa0, nullptr}, HA0, NAUT, 128, 2, 1, 128};
    gemm_all<<<dim3(1, 192), 256>>>(gs);
  }
  {
    GJobs gj; gj.j[0] = makeG(0, HP0, AGGP, nullptr, NPAP);
    gj.j[1] = makeG(2, HA0, AGGA, nullptr, NAUT);
    gather_all<<<dim3((NPAP + 7) / 8, 2), 256>>>(gj);
  }
  {
    GemmJobs gs; gs.njobs = 2;
    gs.j[0] = {{HP0, AGGP, nullptr}, {Ws_p1, Wpp1, nullptr}, HP1, NPAP, 128, 2, 1, 0};
    gs.j[1] = {{HA0, AGGA, nullptr}, {Ws_a1, Waa1, nullptr}, HA1, NAUT, 128, 2, 1, 128};
    gemm_all<<<dim3(1, 192), 256>>>(gs);
  }
  // ---- edge-MLP projections (N=256) ----
  {
    GemmJobs gs; gs.njobs = 4;
    gs.j[0] = {{HP1, nullptr, nullptr}, {Wep1_pp, nullptr, nullptr}, UP, NPAP, 256, 1, 0, 0};
    gs.j[1] = {{HP1, nullptr, nullptr}, {Wep1_pp + 128 * 256, nullptr, nullptr}, VP, NPAP, 256, 1, 0, 128};
    gs.j[2] = {{HA1, nullptr, nullptr}, {Wep1_aa, nullptr, nullptr}, UA, NAUT, 256, 1, 0, 256};
    gs.j[3] = {{HA1, nullptr, nullptr}, {Wep1_aa + 128 * 256, nullptr, nullptr}, VA, NAUT, 256, 1, 0, 320};
    gemm_all<<<dim3(2, 384), 256>>>(gs);
  }
  // ---- prune (fused pp+aa, writes sel + w outputs) ----
  float* out_f = (float*)d_out;
  {
    PruneCfg cp = {OFF + 1 * 4097, P1, UP, VP, bep1_pp, Wep2_pp, bep2_pp,
                   4096, kpp0, kpp1, SELPP, out_f + 5};
    PruneCfg ca = {OFF + 3 * 4097, P3, UA, VA, bep1_aa, Wep2_aa, bep2_aa,
                   2048, kaa0, kaa1, SELAA, out_f + 5 + Epp};
    size_t smem = (4096 + 512) * sizeof(float) + CANDMAX * 8;
    prune_all<<<NPAP + NAUT, 256, smem>>>(cp, ca, NPAP);
  }
  // ---- GNN2 layer 0: sel-gathers, then join side branch, then GEMM ----
  {
    GJobs gj;
    gj.j[0] = makeG(0, x_p, AGGP, SELPP, NPAP);
    gj.j[1] = makeG(2, x_a, AGGA, SELAA, NAUT);
    gather_all<<<dim3((NPAP + 7) / 8, 2), 256>>>(gj);
  }
  cudaStreamWaitEvent(0, e1, 0);
  {
    GemmJobs gs; gs.njobs = 2;
    gs.j[0] = {{x_p, AGGP, AGGP2}, {Ws_p0, Wpp0, Wap0}, HP0, NPAP, 128, 3, 1, 0};
    gs.j[1] = {{x_a, AGGA, AGGA2}, {Ws_a0, Waa0, Wpa0}, HA0, NAUT, 128, 3, 1, 128};
    gemm_all<<<dim3(1, 192), 256>>>(gs);
  }
  // ---- GNN2 layer 1 (node `index`) + classifier ----
  node_out_kernel<<<1, 128>>>(idxPtr, HP0, HA0,
                              OFF + 0 * 4097, P0, SELPP,
                              OFF + 5 * 4097, P5,
                              Ws_p1, Wpp1, Wap1, Wc, bc, out_f);
}

// round 6
// speedup vs baseline: 1.1330x; 1.1330x over previous
#include <cuda_runtime.h>
#include <cstdint>

#define NPAP 4096
#define NAUT 2048
#define HD   128
#define CANDMAX 1024

// ---------------- threefry2x32 (JAX, 20 rounds) ----------------
__host__ __device__ __forceinline__ void tf2x32(unsigned k0, unsigned k1,
                                                unsigned x0, unsigned x1,
                                                unsigned &o0, unsigned &o1) {
  unsigned ks2 = k0 ^ k1 ^ 0x1BD11BDAu;
  x0 += k0; x1 += k1;
#define TFR(r) { x0 += x1; x1 = (x1 << (r)) | (x1 >> (32 - (r))); x1 ^= x0; }
  TFR(13) TFR(15) TFR(26) TFR(6)  x0 += k1;  x1 += ks2 + 1u;
  TFR(17) TFR(29) TFR(16) TFR(24) x0 += ks2; x1 += k0 + 2u;
  TFR(13) TFR(15) TFR(26) TFR(6)  x0 += k0;  x1 += k1 + 3u;
  TFR(17) TFR(29) TFR(16) TFR(24) x0 += k1;  x1 += ks2 + 4u;
  TFR(13) TFR(15) TFR(26) TFR(6)  x0 += ks2; x1 += k0 + 5u;
#undef TFR
  o0 = x0; o1 = x1;
}
__device__ __forceinline__ unsigned jax_bits(unsigned k0, unsigned k1, unsigned m) {
  unsigned o0, o1; tf2x32(k0, k1, 0u, m, o0, o1); return o0 ^ o1;
}

// ---------------- scratch arena ----------------
__device__ __align__(256) unsigned char g_arena[32u * 1024u * 1024u];

// ---------------- CSR build (fused, x8 vectorized) ----------------
struct EdgeJobs {
  const int* key[6]; const int* part[6];
  const int* off[6]; int* cnt[6]; int* cur[6]; int* out[6];
  int pack[6];
  int eStart[7];
};
__global__ void count_all(EdgeJobs ej, int total) {
  int g8 = (blockIdx.x * blockDim.x + threadIdx.x) * 8;
  if (g8 >= total) return;
  int r = 0;
  while (g8 >= ej.eStart[r + 1]) r++;
  int e = g8 - ej.eStart[r];
  int4 k0 = *(const int4*)(ej.key[r] + e);
  int4 k1 = *(const int4*)(ej.key[r] + e + 4);
  int* cnt = ej.cnt[r];
  atomicAdd(&cnt[k0.x], 1); atomicAdd(&cnt[k0.y], 1);
  atomicAdd(&cnt[k0.z], 1); atomicAdd(&cnt[k0.w], 1);
  atomicAdd(&cnt[k1.x], 1); atomicAdd(&cnt[k1.y], 1);
  atomicAdd(&cnt[k1.z], 1); atomicAdd(&cnt[k1.w], 1);
}
__global__ void fill_all(EdgeJobs ej, int total) {
  int g8 = (blockIdx.x * blockDim.x + threadIdx.x) * 8;
  if (g8 >= total) return;
  int r = 0;
  while (g8 >= ej.eStart[r + 1]) r++;
  int e = g8 - ej.eStart[r];
  int4 ka = *(const int4*)(ej.key[r] + e);
  int4 kb = *(const int4*)(ej.key[r] + e + 4);
  int4 pa = *(const int4*)(ej.part[r] + e);
  int4 pb = *(const int4*)(ej.part[r] + e + 4);
  int pk = ej.pack[r];
  const int* off = ej.off[r];
  int* cur = ej.cur[r];
  int* out = ej.out[r];
#define DOF(K, P, EE) { int pos = atomicAdd(&cur[K], 1); \
    out[off[K] + pos] = (P) | (pk ? ((EE) << 12) : 0); }
  DOF(ka.x, pa.x, e)     DOF(ka.y, pa.y, e + 1)
  DOF(ka.z, pa.z, e + 2) DOF(ka.w, pa.w, e + 3)
  DOF(kb.x, pb.x, e + 4) DOF(kb.y, pb.y, e + 5)
  DOF(kb.z, pb.z, e + 6) DOF(kb.w, pb.w, e + 7)
#undef DOF
}
struct ScanArgs { const int* cnt[6]; int* off[6]; int* cur[6]; int n[6]; };
__global__ void scan_kernel(ScanArgs a) {
  int b = blockIdx.x;
  const int* cnt = a.cnt[b]; int* off = a.off[b]; int n = a.n[b];
  __shared__ int part[256];
  int t = threadIdx.x, chunk = (n + 255) / 256, st = t * chunk, s = 0;
  for (int j = 0; j < chunk; j++) { int i = st + j; if (i < n) s += cnt[i]; }
  part[t] = s; __syncthreads();
  for (int d = 1; d < 256; d <<= 1) {
    int v = (t >= d) ? part[t - d] : 0;
    __syncthreads(); part[t] += v; __syncthreads();
  }
  int run = (t == 0) ? 0 : part[t - 1];
  int* cur = a.cur[b];
  for (int j = 0; j < chunk; j++) {
    int i = st + j;
    if (i < n) { off[i] = run; run += cnt[i]; cur[i] = 0; }
  }
  if (t == 255) off[n] = part[255];
}

// ---------------- multi-job mean gather ----------------
struct GJob { const int* off; const int* part; const float* H; float* out;
              const int* sel; int n; };
struct GJobs { GJob j[4]; };
__global__ __launch_bounds__(256) void gather_all(GJobs gj) {
  GJob jb = gj.j[blockIdx.y];
  int node = blockIdx.x * 8 + (threadIdx.x >> 5);
  if (node >= jb.n) return;
  int lane = threadIdx.x & 31;
  int b = jb.off[node], e = jb.off[node + 1];
  float4 acc = make_float4(0.f, 0.f, 0.f, 0.f);
  if (jb.sel) {
    for (int q = b; q < e; ++q) {
      int s = jb.part[q];
      const int* sp = &jb.sel[s * 5];
      if (sp[0] == node || sp[1] == node || sp[2] == node || sp[3] == node ||
          sp[4] == node) {
        float4 v = *((const float4*)(jb.H + (size_t)s * HD) + lane);
        acc.x += v.x; acc.y += v.y; acc.z += v.z; acc.w += v.w;
      }
    }
  } else {
    int q = b;
    for (; q + 4 <= e; q += 4) {
      int s0 = jb.part[q], s1 = jb.part[q + 1];
      int s2 = jb.part[q + 2], s3 = jb.part[q + 3];
      float4 v0 = *((const float4*)(jb.H + (size_t)s0 * HD) + lane);
      float4 v1 = *((const float4*)(jb.H + (size_t)s1 * HD) + lane);
      float4 v2 = *((const float4*)(jb.H + (size_t)s2 * HD) + lane);
      float4 v3 = *((const float4*)(jb.H + (size_t)s3 * HD) + lane);
      acc.x += (v0.x + v1.x) + (v2.x + v3.x);
      acc.y += (v0.y + v1.y) + (v2.y + v3.y);
      acc.z += (v0.z + v1.z) + (v2.z + v3.z);
      acc.w += (v0.w + v1.w) + (v2.w + v3.w);
    }
    for (; q < e; ++q) {
      int s = jb.part[q];
      float4 v = *((const float4*)(jb.H + (size_t)s * HD) + lane);
      acc.x += v.x; acc.y += v.y; acc.z += v.z; acc.w += v.w;
    }
  }
  float inv = 1.f / fmaxf((float)(e - b), 1.f);
  acc.x *= inv; acc.y *= inv; acc.z *= inv; acc.w *= inv;
  *((float4*)(jb.out + (size_t)node * HD) + lane) = acc;
}

// ---- multi-job multi-pair GEMM, f32x2, K=128 fully smem-resident, 64x128 tile ----
// dynamic smem: As[128][68] + Bs[128][132] = 102.4KB; only 2 syncs per pair.
struct GemmJob { const float* A[3]; const float* B[3]; float* C;
                 int M, N, npairs, relu, rbStart; };   // rbStart in 64-row units
struct GemmJobs { GemmJob j[4]; int njobs; };
#define GEMM_SMEM ((128 * 68 + 128 * 132) * 4)
__global__ __launch_bounds__(256) void gemm_all(GemmJobs gjs) {
  extern __shared__ float smg[];
  float (*As)[68]  = (float(*)[68])smg;
  float (*Bs)[132] = (float(*)[132])(smg + 128 * 68);
  int by = blockIdx.y;
  int ji = 0;
  while (ji + 1 < gjs.njobs && by >= gjs.j[ji + 1].rbStart) ji++;
  GemmJob jb = gjs.j[ji];
  int row0 = (by - jb.rbStart) * 64;
  int col0 = blockIdx.x * 128;
  if (col0 >= jb.N) return;
  unsigned long long acc[4][4];
#pragma unroll
  for (int i = 0; i < 4; i++)
#pragma unroll
    for (int j = 0; j < 4; j++) acc[i][j] = 0ull;
  int tid = threadIdx.x;
  int ty = tid >> 4, tx = tid & 15;
  for (int p = 0; p < jb.npairs; p++) {
    const float* A = jb.A[p];
    const float* B = jb.B[p];
    // load A tile 64x128 -> As[k][m]
    {
      int m = tid >> 2, k0 = (tid & 3) * 32;
#pragma unroll
      for (int i = 0; i < 8; i++) {
        float4 v = *(const float4*)(A + (size_t)(row0 + m) * 128 + k0 + i * 4);
        As[k0 + i * 4 + 0][m] = v.x; As[k0 + i * 4 + 1][m] = v.y;
        As[k0 + i * 4 + 2][m] = v.z; As[k0 + i * 4 + 3][m] = v.w;
      }
    }
    // load B tile 128x128 -> Bs[k][n]
    {
      int kk = tid >> 1, n0 = (tid & 1) * 64;
      const float* Brow = B + (size_t)kk * jb.N + col0 + n0;
#pragma unroll
      for (int i = 0; i < 16; i++) {
        float4 v = *(const float4*)(Brow + i * 4);
        Bs[kk][n0 + i * 4 + 0] = v.x; Bs[kk][n0 + i * 4 + 1] = v.y;
        Bs[kk][n0 + i * 4 + 2] = v.z; Bs[kk][n0 + i * 4 + 3] = v.w;
      }
    }
    __syncthreads();
#pragma unroll 4
    for (int k = 0; k < 128; k++) {
      unsigned long long a2[4], b2[4];
#pragma unroll
      for (int i = 0; i < 4; i++) {
        unsigned ai = __float_as_uint(As[k][ty * 4 + i]);
        asm("mov.b64 %0, {%1, %1};" : "=l"(a2[i]) : "r"(ai));
      }
#pragma unroll
      for (int j = 0; j < 4; j++)
        b2[j] = *(const unsigned long long*)&Bs[k][tx * 8 + j * 2];
#pragma unroll
      for (int i = 0; i < 4; i++)
#pragma unroll
        for (int j = 0; j < 4; j++)
          asm("fma.rn.f32x2 %0, %1, %2, %0;" : "+l"(acc[i][j])
              : "l"(a2[i]), "l"(b2[j]));
    }
    if (p + 1 < jb.npairs) __syncthreads();
  }
#pragma unroll
  for (int i = 0; i < 4; i++) {
    int row = row0 + ty * 4 + i;
#pragma unroll
    for (int j = 0; j < 4; j++) {
      unsigned u0, u1;
      asm("mov.b64 {%0, %1}, %2;" : "=r"(u0), "=r"(u1) : "l"(acc[i][j]));
      float c0 = __uint_as_float(u0), c1 = __uint_as_float(u1);
      if (jb.relu) { c0 = fmaxf(c0, 0.f); c1 = fmaxf(c1, 0.f); }
      float2* cp = (float2*)(jb.C + (size_t)row * jb.N + col0 + tx * 8 + j * 2);
      *cp = make_float2(c0, c1);
    }
  }
}

// ------------- prune: edge MLP + coalesce + compact gumbel top-5 + w out -------------
__device__ __forceinline__ unsigned long long packkey(float v, int j) {
  unsigned u = __float_as_uint(v);
  u = (u >> 31) ? ~u : (u | 0x80000000u);
  return (((unsigned long long)u) << 32) |
         (unsigned long long)(0xFFFFFFFFu - (unsigned)j);
}
struct PruneCfg {
  const int* roff; const int* rpart;
  const float* U; const float* V;
  const float* b1; const float* W2; const float* b2;
  int Nc; unsigned k0, k1; int* sel; float* outW;
};
__global__ __launch_bounds__(256) void prune_all(PruneCfg cp, PruneCfg ca, int nPP) {
  PruneCfg cfg = (blockIdx.x < nPP) ? cp : ca;
  int i = (blockIdx.x < nPP) ? blockIdx.x : blockIdx.x - nPP;
  extern __shared__ float sm[];
  float* Arow = sm;                           // Nc
  float* Urow = sm + cfg.Nc;                  // 256
  float* W2c  = Urow + 256;                   // 256
  unsigned long long* cand = (unsigned long long*)(W2c + 256);  // CANDMAX
  __shared__ unsigned long long red[8];
  __shared__ int sel5[5];
  __shared__ int ncand;
  int t = threadIdx.x, warp = t >> 5, lane = t & 31;
  if (t == 0) ncand = 0;
  Urow[t] = cfg.U[(size_t)i * 256 + t] + cfg.b1[t];
  W2c[t] = cfg.W2[2 * t];
  for (int j = t; j < cfg.Nc; j += 256) Arow[j] = 0.f;
  __syncthreads();

  int b = cfg.roff[i], nE = cfg.roff[i + 1] - b;
  float b2v = cfg.b2[0];
  const float4* U4 = (const float4*)&Urow[lane * 8];
  const float4* W4 = (const float4*)&W2c[lane * 8];
  float4 u0 = U4[0], u1 = U4[1], w0 = W4[0], w1 = W4[1];
  for (int e = warp; e < nE; e += 8) {
    int p = cfg.rpart[b + e];
    int d = p & 4095;
    const float4* V4 = (const float4*)(cfg.V + (size_t)d * 256) + lane * 2;
    float4 v0 = V4[0], v1 = V4[1];
    float acc = fmaxf(u0.x + v0.x, 0.f) * w0.x + fmaxf(u0.y + v0.y, 0.f) * w0.y +
                fmaxf(u0.z + v0.z, 0.f) * w0.z + fmaxf(u0.w + v0.w, 0.f) * w0.w +
                fmaxf(u1.x + v1.x, 0.f) * w1.x + fmaxf(u1.y + v1.y, 0.f) * w1.y +
                fmaxf(u1.z + v1.z, 0.f) * w1.z + fmaxf(u1.w + v1.w, 0.f) * w1.w;
#pragma unroll
    for (int o = 16; o; o >>= 1) acc += __shfl_xor_sync(0xffffffffu, acc, o);
    if (lane == 0) atomicAdd(&Arow[d], acc + b2v);
  }
  __syncthreads();

  for (int j = t; j < cfg.Nc; j += 256) {
    float a = Arow[j];
    if (a > 0.f) {
      unsigned m = (unsigned)i * (unsigned)cfg.Nc + (unsigned)j;
      unsigned bits = jax_bits(cfg.k0, cfg.k1, m);
      float f = __uint_as_float((bits >> 9) | 0x3f800000u) - 1.0f;
      float u = fmaxf(1e-10f, f + 1e-10f);
      float y = a + (-logf(-logf(u)));
      int pos = atomicAdd(&ncand, 1);
      if (pos < CANDMAX) cand[pos] = packkey(y, j);
    }
  }
  __syncthreads();
  int nc = ncand < CANDMAX ? ncand : CANDMAX;

  unsigned long long prev = 0;
  for (int r = 0; r < 5; r++) {
    unsigned long long best = 0ull;
    for (int q = t; q < nc; q += 256) {
      unsigned long long k = cand[q];
      if (k == prev) { cand[q] = 0ull; k = 0ull; }
      if (k > best) best = k;
    }
#pragma unroll
    for (int o = 16; o; o >>= 1) {
      unsigned long long v = __shfl_xor_sync(0xffffffffu, best, o);
      if (v > best) best = v;
    }
    if (lane == 0) red[warp] = best;
    __syncthreads();
    if (t == 0) {
      unsigned long long w = red[0];
      for (int q = 1; q < 8; q++) if (red[q] > w) w = red[q];
      red[0] = w;
      sel5[r] = (w != 0ull) ? (int)(0xFFFFFFFFu - (unsigned)(w & 0xFFFFFFFFull)) : -1;
    }
    __syncthreads();
    prev = red[0];
    __syncthreads();
  }
  if (t == 0) {
    int r = 0;
    while (r < 5 && sel5[r] >= 0) r++;
    for (int j = 0; j < cfg.Nc && r < 5; j++)
      if (!(Arow[j] > 0.f)) sel5[r++] = j;
    for (int q = 0; q < 5; q++) cfg.sel[i * 5 + q] = sel5[q];
  }
  __syncthreads();

  int s0 = sel5[0], s1 = sel5[1], s2 = sel5[2], s3 = sel5[3], s4 = sel5[4];
  for (int e = t; e < nE; e += 256) {
    int p = cfg.rpart[b + e];
    int d = p & 4095;
    int eid = p >> 12;
    cfg.outW[eid] = (d == s0 || d == s1 || d == s2 || d == s3 || d == s4) ? 1.f : 0.f;
  }
}

// ---------------- GNN2 layer1 for node `index` + classifier ----------------
__global__ __launch_bounds__(128) void node_out_kernel(
    const int* __restrict__ idxPtr,
    const float* __restrict__ HP0, const float* __restrict__ HA0,
    const int* __restrict__ ppoff, const int* __restrict__ pppart,
    const int* __restrict__ selpp,
    const int* __restrict__ apoff, const int* __restrict__ appart,
    const float* __restrict__ Wself, const float* __restrict__ Wpp1,
    const float* __restrict__ Wap1,
    const float* __restrict__ Wc, const float* __restrict__ bc,
    float* __restrict__ out) {
  __shared__ float selfv[128], mpp[128], mapv[128], agg[128];
  int t = threadIdx.x;
  int idx = idxPtr[0];
  selfv[t] = HP0[(size_t)idx * HD + t];
  int b = ppoff[idx], e = ppoff[idx + 1];
  float s = 0.f;
  for (int q = b; q < e; q++) {
    int sn = pppart[q];
    const int* sp = &selpp[sn * 5];
    if (sp[0] == idx || sp[1] == idx || sp[2] == idx || sp[3] == idx || sp[4] == idx)
      s += HP0[(size_t)sn * HD + t];
  }
  mpp[t] = s / fmaxf((float)(e - b), 1.f);
  b = apoff[idx]; e = apoff[idx + 1];
  s = 0.f;
  for (int q = b; q < e; q++) s += HA0[(size_t)appart[q] * HD + t];
  mapv[t] = s / fmaxf((float)(e - b), 1.f);
  __syncthreads();
  float a = 0.f;
  for (int k = 0; k < HD; k++)
    a += selfv[k] * Wself[k * HD + t] + mpp[k] * Wpp1[k * HD + t] +
         mapv[k] * Wap1[k * HD + t];
  agg[t] = fmaxf(a, 0.f);
  __syncthreads();
  if (t < 5) {
    float y = bc[t];
    for (int k = 0; k < HD; k++) y += agg[k] * Wc[k * 5 + t];
    out[t] = y;
  }
}

// ---------------- host launcher ----------------
extern "C" void kernel_launch(void* const* d_in, const int* in_sizes, int n_in,
                              void* d_out, int out_size) {
  const float* x_p = (const float*)d_in[0];
  const float* x_a = (const float*)d_in[1];
  const int* ei_pp = (const int*)d_in[2];
  const int* ei_aa = (const int*)d_in[3];
  const int* ei_pa = (const int*)d_in[4];
  const int* ei_ap = (const int*)d_in[5];
  const int* idxPtr = (const int*)d_in[8];
  const float* Ws_p0 = (const float*)d_in[9];
  const float* Ws_p1 = (const float*)d_in[10];
  const float* Ws_a0 = (const float*)d_in[11];
  const float* Ws_a1 = (const float*)d_in[12];
  const float* Wpp0 = (const float*)d_in[13];
  const float* Wpp1 = (const float*)d_in[14];
  const float* Waa0 = (const float*)d_in[15];
  const float* Waa1 = (const float*)d_in[16];
  const float* Wpa0 = (const float*)d_in[17];
  const float* Wap0 = (const float*)d_in[19];
  const float* Wap1 = (const float*)d_in[20];
  const float* Wep1_pp = (const float*)d_in[21];
  const float* bep1_pp = (const float*)d_in[22];
  const float* Wep2_pp = (const float*)d_in[23];
  const float* bep2_pp = (const float*)d_in[24];
  const float* Wep1_aa = (const float*)d_in[25];
  const float* bep1_aa = (const float*)d_in[26];
  const float* Wep2_aa = (const float*)d_in[27];
  const float* bep2_aa = (const float*)d_in[28];
  const float* Wc = (const float*)d_in[29];
  const float* bc = (const float*)d_in[30];

  int Epp = in_sizes[2] / 2, Eaa = in_sizes[3] / 2;
  int Epa = in_sizes[4] / 2, Eap = in_sizes[5] / 2;
  const int* pp_src = ei_pp;  const int* pp_dst = ei_pp + Epp;
  const int* aa_src = ei_aa;  const int* aa_dst = ei_aa + Eaa;
  const int* pa_src = ei_pa;  const int* pa_dst = ei_pa + Epa;
  const int* ap_src = ei_ap;  const int* ap_dst = ei_ap + Eap;

  unsigned kpp0, kpp1, kaa0, kaa1;
  tf2x32(0u, 42u, 0u, 0u, kpp0, kpp1);
  tf2x32(0u, 42u, 0u, 1u, kaa0, kaa1);

  cudaFuncSetAttribute(gemm_all, cudaFuncAttributeMaxDynamicSharedMemorySize,
                       GEMM_SMEM);

  void* basep = nullptr;
  cudaGetSymbolAddress(&basep, g_arena);
  unsigned char* ar = (unsigned char*)basep;
  size_t off = 0;
  auto carve = [&](size_t bytes) -> unsigned char* {
    unsigned char* p = ar + off;
    off += (bytes + 255) & ~(size_t)255;
    return p;
  };
  float* AGGP  = (float*)carve((size_t)NPAP * HD * 4);
  float* AGGA  = (float*)carve((size_t)NAUT * HD * 4);
  float* AGGP2 = (float*)carve((size_t)NPAP * HD * 4);
  float* AGGA2 = (float*)carve((size_t)NAUT * HD * 4);
  float* HP0 = (float*)carve((size_t)NPAP * HD * 4);
  float* HP1 = (float*)carve((size_t)NPAP * HD * 4);
  float* HA0 = (float*)carve((size_t)NAUT * HD * 4);
  float* HA1 = (float*)carve((size_t)NAUT * HD * 4);
  float* UP = (float*)carve((size_t)NPAP * 256 * 4);
  float* VP = (float*)carve((size_t)NPAP * 256 * 4);
  float* UA = (float*)carve((size_t)NAUT * 256 * 4);
  float* VA = (float*)carve((size_t)NAUT * 256 * 4);
  int* CNT = (int*)carve(6 * 4096 * 4);
  int* CUR = (int*)carve(6 * 4096 * 4);
  int* OFF = (int*)carve(6 * 4097 * 4);
  int* P0 = (int*)carve((size_t)Epp * 4);
  int* P1 = (int*)carve((size_t)Epp * 4);
  int* P2 = (int*)carve((size_t)Eaa * 4);
  int* P3 = (int*)carve((size_t)Eaa * 4);
  int* P4 = (int*)carve((size_t)Epa * 4);
  int* P5 = (int*)carve((size_t)Eap * 4);
  int* SELPP = (int*)carve((size_t)NPAP * 5 * 4);
  int* SELAA = (int*)carve((size_t)NAUT * 5 * 4);

  EdgeJobs ej;
  const int* keys[6]  = {pp_dst, pp_src, aa_dst, aa_src, pa_dst, ap_dst};
  const int* parts[6] = {pp_src, pp_dst, aa_src, aa_dst, pa_src, ap_src};
  int ns[6] = {NPAP, NPAP, NAUT, NAUT, NAUT, NPAP};
  int Es[6] = {Epp, Epp, Eaa, Eaa, Epa, Eap};
  int packs[6] = {0, 1, 0, 1, 0, 0};
  int* outs[6] = {P0, P1, P2, P3, P4, P5};
  int run = 0;
  for (int r = 0; r < 6; r++) {
    ej.key[r] = keys[r]; ej.part[r] = parts[r];
    ej.off[r] = OFF + r * 4097;
    ej.cnt[r] = CNT + r * 4096; ej.cur[r] = CUR + r * 4096;
    ej.out[r] = outs[r]; ej.pack[r] = packs[r];
    ej.eStart[r] = run; run += Es[r];
  }
  ej.eStart[6] = run;
  cudaMemsetAsync(CNT, 0, 6 * 4096 * 4);
  count_all<<<(run / 8 + 255) / 256, 256>>>(ej, run);
  {
    ScanArgs sa;
    for (int r = 0; r < 6; r++) {
      sa.cnt[r] = CNT + r * 4096; sa.off[r] = OFF + r * 4097;
      sa.cur[r] = CUR + r * 4096; sa.n[r] = ns[r];
    }
    scan_kernel<<<6, 256>>>(sa);
  }
  fill_all<<<(run / 8 + 255) / 256, 256>>>(ej, run);

  auto makeG = [&](int csr, const float* H, float* o, const int* sel, int n) {
    GJob j; j.off = OFF + csr * 4097; j.part = outs[csr]; j.H = H; j.out = o;
    j.sel = sel; j.n = n; return j;
  };

  // ---- GNN1 ----
  {
    GJobs gj; gj.j[0] = makeG(0, x_p, AGGP, nullptr, NPAP);
    gj.j[1] = makeG(2, x_a, AGGA, nullptr, NAUT);
    gather_all<<<dim3((NPAP + 7) / 8, 2), 256>>>(gj);
  }
  {
    GemmJobs gs; gs.njobs = 2;
    gs.j[0] = {{x_p, AGGP, nullptr}, {Ws_p0, Wpp0, nullptr}, HP0, NPAP, 128, 2, 1, 0};
    gs.j[1] = {{x_a, AGGA, nullptr}, {Ws_a0, Waa0, nullptr}, HA0, NAUT, 128, 2, 1, 64};
    gemm_all<<<dim3(1, 96), 256, GEMM_SMEM>>>(gs);
  }
  {
    GJobs gj; gj.j[0] = makeG(0, HP0, AGGP, nullptr, NPAP);
    gj.j[1] = makeG(2, HA0, AGGA, nullptr, NAUT);
    gather_all<<<dim3((NPAP + 7) / 8, 2), 256>>>(gj);
  }
  {
    GemmJobs gs; gs.njobs = 2;
    gs.j[0] = {{HP0, AGGP, nullptr}, {Ws_p1, Wpp1, nullptr}, HP1, NPAP, 128, 2, 1, 0};
    gs.j[1] = {{HA0, AGGA, nullptr}, {Ws_a1, Waa1, nullptr}, HA1, NAUT, 128, 2, 1, 64};
    gemm_all<<<dim3(1, 96), 256, GEMM_SMEM>>>(gs);
  }
  // ---- edge-MLP projections (N=256) ----
  {
    GemmJobs gs; gs.njobs = 4;
    gs.j[0] = {{HP1, nullptr, nullptr}, {Wep1_pp, nullptr, nullptr}, UP, NPAP, 256, 1, 0, 0};
    gs.j[1] = {{HP1, nullptr, nullptr}, {Wep1_pp + 128 * 256, nullptr, nullptr}, VP, NPAP, 256, 1, 0, 64};
    gs.j[2] = {{HA1, nullptr, nullptr}, {Wep1_aa, nullptr, nullptr}, UA, NAUT, 256, 1, 0, 128};
    gs.j[3] = {{HA1, nullptr, nullptr}, {Wep1_aa + 128 * 256, nullptr, nullptr}, VA, NAUT, 256, 1, 0, 160};
    gemm_all<<<dim3(2, 192), 256, GEMM_SMEM>>>(gs);
  }
  // ---- prune (fused pp+aa, writes sel + w outputs) ----
  float* out_f = (float*)d_out;
  {
    PruneCfg cp = {OFF + 1 * 4097, P1, UP, VP, bep1_pp, Wep2_pp, bep2_pp,
                   4096, kpp0, kpp1, SELPP, out_f + 5};
    PruneCfg ca = {OFF + 3 * 4097, P3, UA, VA, bep1_aa, Wep2_aa, bep2_aa,
                   2048, kaa0, kaa1, SELAA, out_f + 5 + Epp};
    size_t smem = (4096 + 512) * sizeof(float) + CANDMAX * 8;
    prune_all<<<NPAP + NAUT, 256, smem>>>(cp, ca, NPAP);
  }
  // ---- GNN2 layer 0 ----
  {
    GJobs gj;
    gj.j[0] = makeG(0, x_p, AGGP, SELPP, NPAP);
    gj.j[1] = makeG(5, x_a, AGGP2, nullptr, NPAP);
    gj.j[2] = makeG(2, x_a, AGGA, SELAA, NAUT);
    gj.j[3] = makeG(4, x_p, AGGA2, nullptr, NAUT);
    gather_all<<<dim3((NPAP + 7) / 8, 4), 256>>>(gj);
  }
  {
    GemmJobs gs; gs.njobs = 2;
    gs.j[0] = {{x_p, AGGP, AGGP2}, {Ws_p0, Wpp0, Wap0}, HP0, NPAP, 128, 3, 1, 0};
    gs.j[1] = {{x_a, AGGA, AGGA2}, {Ws_a0, Waa0, Wpa0}, HA0, NAUT, 128, 3, 1, 64};
    gemm_all<<<dim3(1, 96), 256, GEMM_SMEM>>>(gs);
  }
  // ---- GNN2 layer 1 (node `index`) + classifier ----
  node_out_kernel<<<1, 128>>>(idxPtr, HP0, HA0,
                              OFF + 0 * 4097, P0, SELPP,
                              OFF + 5 * 4097, P5,
                              Ws_p1, Wpp1, Wap1, Wc, bc, out_f);
}

// round 7
// speedup vs baseline: 1.2519x; 1.1050x over previous
#include <cuda_runtime.h>
#include <cstdint>

#define NPAP 4096
#define NAUT 2048
#define HD   128
#define CANDMAX 1024

// ---------------- threefry2x32 (JAX, 20 rounds) ----------------
__host__ __device__ __forceinline__ void tf2x32(unsigned k0, unsigned k1,
                                                unsigned x0, unsigned x1,
                                                unsigned &o0, unsigned &o1) {
  unsigned ks2 = k0 ^ k1 ^ 0x1BD11BDAu;
  x0 += k0; x1 += k1;
#define TFR(r) { x0 += x1; x1 = (x1 << (r)) | (x1 >> (32 - (r))); x1 ^= x0; }
  TFR(13) TFR(15) TFR(26) TFR(6)  x0 += k1;  x1 += ks2 + 1u;
  TFR(17) TFR(29) TFR(16) TFR(24) x0 += ks2; x1 += k0 + 2u;
  TFR(13) TFR(15) TFR(26) TFR(6)  x0 += k0;  x1 += k1 + 3u;
  TFR(17) TFR(29) TFR(16) TFR(24) x0 += k1;  x1 += ks2 + 4u;
  TFR(13) TFR(15) TFR(26) TFR(6)  x0 += ks2; x1 += k0 + 5u;
#undef TFR
  o0 = x0; o1 = x1;
}
__device__ __forceinline__ unsigned jax_bits(unsigned k0, unsigned k1, unsigned m) {
  unsigned o0, o1; tf2x32(k0, k1, 0u, m, o0, o1); return o0 ^ o1;
}

// ---------------- scratch arena ----------------
__device__ __align__(256) unsigned char g_arena[32u * 1024u * 1024u];

// ---------------- CSR build (fused, x8 vectorized) ----------------
struct EdgeJobs {
  const int* key[6]; const int* part[6];
  const int* off[6]; int* cnt[6]; int* cur[6]; int* out[6];
  int pack[6];
  int eStart[7];
};
__global__ void count_all(EdgeJobs ej, int total) {
  int g8 = (blockIdx.x * blockDim.x + threadIdx.x) * 8;
  if (g8 >= total) return;
  int r = 0;
  while (g8 >= ej.eStart[r + 1]) r++;
  int e = g8 - ej.eStart[r];
  int4 k0 = *(const int4*)(ej.key[r] + e);
  int4 k1 = *(const int4*)(ej.key[r] + e + 4);
  int* cnt = ej.cnt[r];
  atomicAdd(&cnt[k0.x], 1); atomicAdd(&cnt[k0.y], 1);
  atomicAdd(&cnt[k0.z], 1); atomicAdd(&cnt[k0.w], 1);
  atomicAdd(&cnt[k1.x], 1); atomicAdd(&cnt[k1.y], 1);
  atomicAdd(&cnt[k1.z], 1); atomicAdd(&cnt[k1.w], 1);
}
__global__ void fill_all(EdgeJobs ej, int total) {
  int g8 = (blockIdx.x * blockDim.x + threadIdx.x) * 8;
  if (g8 >= total) return;
  int r = 0;
  while (g8 >= ej.eStart[r + 1]) r++;
  int e = g8 - ej.eStart[r];
  int4 ka = *(const int4*)(ej.key[r] + e);
  int4 kb = *(const int4*)(ej.key[r] + e + 4);
  int4 pa = *(const int4*)(ej.part[r] + e);
  int4 pb = *(const int4*)(ej.part[r] + e + 4);
  int pk = ej.pack[r];
  const int* off = ej.off[r];
  int* cur = ej.cur[r];
  int* out = ej.out[r];
#define DOF(K, P, EE) { int pos = atomicAdd(&cur[K], 1); \
    out[off[K] + pos] = (P) | (pk ? ((EE) << 12) : 0); }
  DOF(ka.x, pa.x, e)     DOF(ka.y, pa.y, e + 1)
  DOF(ka.z, pa.z, e + 2) DOF(ka.w, pa.w, e + 3)
  DOF(kb.x, pb.x, e + 4) DOF(kb.y, pb.y, e + 5)
  DOF(kb.z, pb.z, e + 6) DOF(kb.w, pb.w, e + 7)
#undef DOF
}
struct ScanArgs { const int* cnt[6]; int* off[6]; int* cur[6]; int n[6]; };
__global__ void scan_kernel(ScanArgs a) {
  int b = blockIdx.x;
  const int* cnt = a.cnt[b]; int* off = a.off[b]; int n = a.n[b];
  __shared__ int part[256];
  int t = threadIdx.x, chunk = (n + 255) / 256, st = t * chunk, s = 0;
  for (int j = 0; j < chunk; j++) { int i = st + j; if (i < n) s += cnt[i]; }
  part[t] = s; __syncthreads();
  for (int d = 1; d < 256; d <<= 1) {
    int v = (t >= d) ? part[t - d] : 0;
    __syncthreads(); part[t] += v; __syncthreads();
  }
  int run = (t == 0) ? 0 : part[t - 1];
  int* cur = a.cur[b];
  for (int j = 0; j < chunk; j++) {
    int i = st + j;
    if (i < n) { off[i] = run; run += cnt[i]; cur[i] = 0; }
  }
  if (t == 255) off[n] = part[255];
}

// ---------------- multi-job mean gather ----------------
struct GJob { const int* off; const int* part; const float* H; float* out;
              const int* sel; int n; };
struct GJobs { GJob j[4]; };
__global__ __launch_bounds__(256) void gather_all(GJobs gj) {
  GJob jb = gj.j[blockIdx.y];
  int node = blockIdx.x * 8 + (threadIdx.x >> 5);
  if (node >= jb.n) return;
  int lane = threadIdx.x & 31;
  int b = jb.off[node], e = jb.off[node + 1];
  float4 acc = make_float4(0.f, 0.f, 0.f, 0.f);
  if (jb.sel) {
    for (int q = b; q < e; ++q) {
      int s = jb.part[q];
      const int* sp = &jb.sel[s * 5];
      if (sp[0] == node || sp[1] == node || sp[2] == node || sp[3] == node ||
          sp[4] == node) {
        float4 v = *((const float4*)(jb.H + (size_t)s * HD) + lane);
        acc.x += v.x; acc.y += v.y; acc.z += v.z; acc.w += v.w;
      }
    }
  } else {
    int q = b;
    for (; q + 4 <= e; q += 4) {
      int s0 = jb.part[q], s1 = jb.part[q + 1];
      int s2 = jb.part[q + 2], s3 = jb.part[q + 3];
      float4 v0 = *((const float4*)(jb.H + (size_t)s0 * HD) + lane);
      float4 v1 = *((const float4*)(jb.H + (size_t)s1 * HD) + lane);
      float4 v2 = *((const float4*)(jb.H + (size_t)s2 * HD) + lane);
      float4 v3 = *((const float4*)(jb.H + (size_t)s3 * HD) + lane);
      acc.x += (v0.x + v1.x) + (v2.x + v3.x);
      acc.y += (v0.y + v1.y) + (v2.y + v3.y);
      acc.z += (v0.z + v1.z) + (v2.z + v3.z);
      acc.w += (v0.w + v1.w) + (v2.w + v3.w);
    }
    for (; q < e; ++q) {
      int s = jb.part[q];
      float4 v = *((const float4*)(jb.H + (size_t)s * HD) + lane);
      acc.x += v.x; acc.y += v.y; acc.z += v.z; acc.w += v.w;
    }
  }
  float inv = 1.f / fmaxf((float)(e - b), 1.f);
  acc.x *= inv; acc.y *= inv; acc.z *= inv; acc.w *= inv;
  *((float4*)(jb.out + (size_t)node * HD) + lane) = acc;
}

// ---------------- multi-job multi-pair GEMM, f32x2, K=128, 64x128 tile (R4) ----------------
struct GemmJob { const float* A[3]; const float* B[3]; float* C;
                 int M, N, npairs, relu, rbStart; };   // rbStart in 64-row units
struct GemmJobs { GemmJob j[4]; int njobs; };
__global__ __launch_bounds__(256) void gemm_all(GemmJobs gjs) {
  int by = blockIdx.y;
  int ji = 0;
  while (ji + 1 < gjs.njobs && by >= gjs.j[ji + 1].rbStart) ji++;
  GemmJob jb = gjs.j[ji];
  int row0 = (by - jb.rbStart) * 64;
  int col0 = blockIdx.x * 128;
  if (col0 >= jb.N) return;
  __shared__ float As[16][68];
  __shared__ float Bs[16][132];
  unsigned long long acc[4][4];
#pragma unroll
  for (int i = 0; i < 4; i++)
#pragma unroll
    for (int j = 0; j < 4; j++) acc[i][j] = 0ull;
  int tid = threadIdx.x;
  int ty = tid >> 4, tx = tid & 15;
  for (int p = 0; p < jb.npairs; p++) {
    const float* A = jb.A[p];
    const float* B = jb.B[p];
    for (int kt = 0; kt < 128; kt += 16) {
      {
        int m = tid >> 2, kk = (tid & 3) * 4;
        float4 v = *(const float4*)(A + (size_t)(row0 + m) * 128 + kt + kk);
        As[kk][m] = v.x; As[kk + 1][m] = v.y; As[kk + 2][m] = v.z; As[kk + 3][m] = v.w;
      }
#pragma unroll
      for (int q = 0; q < 2; q++) {
        int li = tid * 2 + q;
        int kk = li >> 5;
        int n4 = (li & 31) * 4;
        float4 v = *(const float4*)(B + (size_t)(kt + kk) * jb.N + col0 + n4);
        Bs[kk][n4] = v.x; Bs[kk][n4 + 1] = v.y; Bs[kk][n4 + 2] = v.z; Bs[kk][n4 + 3] = v.w;
      }
      __syncthreads();
#pragma unroll
      for (int k = 0; k < 16; k++) {
        unsigned long long a2[4], b2[4];
#pragma unroll
        for (int i = 0; i < 4; i++) {
          unsigned ai = __float_as_uint(As[k][ty * 4 + i]);
          asm("mov.b64 %0, {%1, %1};" : "=l"(a2[i]) : "r"(ai));
        }
#pragma unroll
        for (int j = 0; j < 4; j++)
          b2[j] = *(const unsigned long long*)&Bs[k][tx * 8 + j * 2];
#pragma unroll
        for (int i = 0; i < 4; i++)
#pragma unroll
          for (int j = 0; j < 4; j++)
            asm("fma.rn.f32x2 %0, %1, %2, %0;" : "+l"(acc[i][j])
                : "l"(a2[i]), "l"(b2[j]));
      }
      __syncthreads();
    }
  }
#pragma unroll
  for (int i = 0; i < 4; i++) {
    int row = row0 + ty * 4 + i;
#pragma unroll
    for (int j = 0; j < 4; j++) {
      unsigned u0, u1;
      asm("mov.b64 {%0, %1}, %2;" : "=r"(u0), "=r"(u1) : "l"(acc[i][j]));
      float c0 = __uint_as_float(u0), c1 = __uint_as_float(u1);
      if (jb.relu) { c0 = fmaxf(c0, 0.f); c1 = fmaxf(c1, 0.f); }
      float2* cp = (float2*)(jb.C + (size_t)row * jb.N + col0 + tx * 8 + j * 2);
      *cp = make_float2(c0, c1);
    }
  }
}

// ------------- prune: edge MLP + coalesce + compact gumbel top-5 + w out -------------
__device__ __forceinline__ unsigned long long packkey(float v, int j) {
  unsigned u = __float_as_uint(v);
  u = (u >> 31) ? ~u : (u | 0x80000000u);
  return (((unsigned long long)u) << 32) |
         (unsigned long long)(0xFFFFFFFFu - (unsigned)j);
}
struct PruneCfg {
  const int* roff; const int* rpart;
  const float* U; const float* V;
  const float* b1; const float* W2; const float* b2;
  int Nc; unsigned k0, k1; int* sel; float* outW;
};
__global__ __launch_bounds__(256) void prune_all(PruneCfg cp, PruneCfg ca, int nPP) {
  PruneCfg cfg = (blockIdx.x < nPP) ? cp : ca;
  int i = (blockIdx.x < nPP) ? blockIdx.x : blockIdx.x - nPP;
  extern __shared__ float sm[];
  float* Arow = sm;                           // Nc
  float* Urow = sm + cfg.Nc;                  // 256
  float* W2c  = Urow + 256;                   // 256
  unsigned long long* cand = (unsigned long long*)(W2c + 256);  // CANDMAX
  __shared__ int sel5[5];
  __shared__ int ncand;
  int t = threadIdx.x, warp = t >> 5, lane = t & 31;
  if (t == 0) ncand = 0;
  Urow[t] = cfg.U[(size_t)i * 256 + t] + cfg.b1[t];
  W2c[t] = cfg.W2[2 * t];
  {
    float4* Az = (float4*)Arow;
    int n4 = cfg.Nc >> 2;
    for (int j = t; j < n4; j += 256) Az[j] = make_float4(0.f, 0.f, 0.f, 0.f);
  }
  __syncthreads();

  int b = cfg.roff[i], nE = cfg.roff[i + 1] - b;
  float b2v = cfg.b2[0];
  const float4* U4 = (const float4*)&Urow[lane * 8];
  const float4* W4 = (const float4*)&W2c[lane * 8];
  float4 u0 = U4[0], u1 = U4[1], w0 = W4[0], w1 = W4[1];
  // edge-MLP, 2 edges in flight per warp per iter
  for (int e = warp; e < nE; e += 16) {
    int p1 = cfg.rpart[b + e];
    int d1 = p1 & 4095;
    int e2 = e + 8;
    bool has2 = (e2 < nE);
    int p2 = has2 ? cfg.rpart[b + e2] : p1;
    int d2 = p2 & 4095;
    const float4* V1 = (const float4*)(cfg.V + (size_t)d1 * 256) + lane * 2;
    const float4* V2 = (const float4*)(cfg.V + (size_t)d2 * 256) + lane * 2;
    float4 a0 = V1[0], a1 = V1[1];
    float4 c0 = V2[0], c1 = V2[1];
    float acc1 = fmaxf(u0.x + a0.x, 0.f) * w0.x + fmaxf(u0.y + a0.y, 0.f) * w0.y +
                 fmaxf(u0.z + a0.z, 0.f) * w0.z + fmaxf(u0.w + a0.w, 0.f) * w0.w +
                 fmaxf(u1.x + a1.x, 0.f) * w1.x + fmaxf(u1.y + a1.y, 0.f) * w1.y +
                 fmaxf(u1.z + a1.z, 0.f) * w1.z + fmaxf(u1.w + a1.w, 0.f) * w1.w;
    float acc2 = fmaxf(u0.x + c0.x, 0.f) * w0.x + fmaxf(u0.y + c0.y, 0.f) * w0.y +
                 fmaxf(u0.z + c0.z, 0.f) * w0.z + fmaxf(u0.w + c0.w, 0.f) * w0.w +
                 fmaxf(u1.x + c1.x, 0.f) * w1.x + fmaxf(u1.y + c1.y, 0.f) * w1.y +
                 fmaxf(u1.z + c1.z, 0.f) * w1.z + fmaxf(u1.w + c1.w, 0.f) * w1.w;
#pragma unroll
    for (int o = 16; o; o >>= 1) {
      acc1 += __shfl_xor_sync(0xffffffffu, acc1, o);
      acc2 += __shfl_xor_sync(0xffffffffu, acc2, o);
    }
    if (lane == 0) {
      atomicAdd(&Arow[d1], acc1 + b2v);
      if (has2) atomicAdd(&Arow[d2], acc2 + b2v);
    }
  }
  __syncthreads();

  // candidates: entries with A>0 get gumbel noise (vectorized scan)
  {
    const float4* Az = (const float4*)Arow;
    int n4 = cfg.Nc >> 2;
    for (int j4 = t; j4 < n4; j4 += 256) {
      float4 a = Az[j4];
      if (a.x > 0.f || a.y > 0.f || a.z > 0.f || a.w > 0.f) {
        float av[4] = {a.x, a.y, a.z, a.w};
#pragma unroll
        for (int c = 0; c < 4; c++) {
          if (av[c] > 0.f) {
            int j = j4 * 4 + c;
            unsigned m = (unsigned)i * (unsigned)cfg.Nc + (unsigned)j;
            unsigned bits = jax_bits(cfg.k0, cfg.k1, m);
            float f = __uint_as_float((bits >> 9) | 0x3f800000u) - 1.0f;
            float u = fmaxf(1e-10f, f + 1e-10f);
            float y = av[c] + (-logf(-logf(u)));
            int pos = atomicAdd(&ncand, 1);
            if (pos < CANDMAX) cand[pos] = packkey(y, j);
          }
        }
      }
    }
  }
  __syncthreads();
  int nc = ncand < CANDMAX ? ncand : CANDMAX;

  // top-5 entirely within warp 0 (no block barriers inside)
  if (warp == 0) {
    unsigned long long prev = 0;
    for (int r = 0; r < 5; r++) {
      unsigned long long best = 0ull;
      for (int q = lane; q < nc; q += 32) {
        unsigned long long k = cand[q];
        if (k == prev) { cand[q] = 0ull; k = 0ull; }
        if (k > best) best = k;
      }
#pragma unroll
      for (int o = 16; o; o >>= 1) {
        unsigned long long v = __shfl_xor_sync(0xffffffffu, best, o);
        if (v > best) best = v;
      }
      if (lane == 0)
        sel5[r] = (best != 0ull) ? (int)(0xFFFFFFFFu - (unsigned)(best & 0xFFFFFFFFull))
                                 : -1;
      prev = best;
    }
    if (lane == 0) {
      int r = 0;
      while (r < 5 && sel5[r] >= 0) r++;
      for (int j = 0; j < cfg.Nc && r < 5; j++)
        if (!(Arow[j] > 0.f)) sel5[r++] = j;
      for (int q = 0; q < 5; q++) cfg.sel[i * 5 + q] = sel5[q];
    }
  }
  __syncthreads();

  int s0 = sel5[0], s1 = sel5[1], s2 = sel5[2], s3 = sel5[3], s4 = sel5[4];
  for (int e = t; e < nE; e += 256) {
    int p = cfg.rpart[b + e];
    int d = p & 4095;
    int eid = p >> 12;
    cfg.outW[eid] = (d == s0 || d == s1 || d == s2 || d == s3 || d == s4) ? 1.f : 0.f;
  }
}

// ---------------- GNN2 layer1 for node `index` + classifier ----------------
__global__ __launch_bounds__(128) void node_out_kernel(
    const int* __restrict__ idxPtr,
    const float* __restrict__ HP0, const float* __restrict__ HA0,
    const int* __restrict__ ppoff, const int* __restrict__ pppart,
    const int* __restrict__ selpp,
    const int* __restrict__ apoff, const int* __restrict__ appart,
    const float* __restrict__ Wself, const float* __restrict__ Wpp1,
    const float* __restrict__ Wap1,
    const float* __restrict__ Wc, const float* __restrict__ bc,
    float* __restrict__ out) {
  __shared__ float selfv[128], mpp[128], mapv[128], agg[128];
  int t = threadIdx.x;
  int idx = idxPtr[0];
  selfv[t] = HP0[(size_t)idx * HD + t];
  int b = ppoff[idx], e = ppoff[idx + 1];
  float s = 0.f;
  for (int q = b; q < e; q++) {
    int sn = pppart[q];
    const int* sp = &selpp[sn * 5];
    if (sp[0] == idx || sp[1] == idx || sp[2] == idx || sp[3] == idx || sp[4] == idx)
      s += HP0[(size_t)sn * HD + t];
  }
  mpp[t] = s / fmaxf((float)(e - b), 1.f);
  b = apoff[idx]; e = apoff[idx + 1];
  s = 0.f;
  for (int q = b; q < e; q++) s += HA0[(size_t)appart[q] * HD + t];
  mapv[t] = s / fmaxf((float)(e - b), 1.f);
  __syncthreads();
  float a = 0.f;
  for (int k = 0; k < HD; k++)
    a += selfv[k] * Wself[k * HD + t] + mpp[k] * Wpp1[k * HD + t] +
         mapv[k] * Wap1[k * HD + t];
  agg[t] = fmaxf(a, 0.f);
  __syncthreads();
  if (t < 5) {
    float y = bc[t];
    for (int k = 0; k < HD; k++) y += agg[k] * Wc[k * 5 + t];
    out[t] = y;
  }
}

// ---------------- host launcher ----------------
extern "C" void kernel_launch(void* const* d_in, const int* in_sizes, int n_in,
                              void* d_out, int out_size) {
  const float* x_p = (const float*)d_in[0];
  const float* x_a = (const float*)d_in[1];
  const int* ei_pp = (const int*)d_in[2];
  const int* ei_aa = (const int*)d_in[3];
  const int* ei_pa = (const int*)d_in[4];
  const int* ei_ap = (const int*)d_in[5];
  const int* idxPtr = (const int*)d_in[8];
  const float* Ws_p0 = (const float*)d_in[9];
  const float* Ws_p1 = (const float*)d_in[10];
  const float* Ws_a0 = (const float*)d_in[11];
  const float* Ws_a1 = (const float*)d_in[12];
  const float* Wpp0 = (const float*)d_in[13];
  const float* Wpp1 = (const float*)d_in[14];
  const float* Waa0 = (const float*)d_in[15];
  const float* Waa1 = (const float*)d_in[16];
  const float* Wpa0 = (const float*)d_in[17];
  const float* Wap0 = (const float*)d_in[19];
  const float* Wap1 = (const float*)d_in[20];
  const float* Wep1_pp = (const float*)d_in[21];
  const float* bep1_pp = (const float*)d_in[22];
  const float* Wep2_pp = (const float*)d_in[23];
  const float* bep2_pp = (const float*)d_in[24];
  const float* Wep1_aa = (const float*)d_in[25];
  const float* bep1_aa = (const float*)d_in[26];
  const float* Wep2_aa = (const float*)d_in[27];
  const float* bep2_aa = (const float*)d_in[28];
  const float* Wc = (const float*)d_in[29];
  const float* bc = (const float*)d_in[30];

  int Epp = in_sizes[2] / 2, Eaa = in_sizes[3] / 2;
  int Epa = in_sizes[4] / 2, Eap = in_sizes[5] / 2;
  const int* pp_src = ei_pp;  const int* pp_dst = ei_pp + Epp;
  const int* aa_src = ei_aa;  const int* aa_dst = ei_aa + Eaa;
  const int* pa_src = ei_pa;  const int* pa_dst = ei_pa + Epa;
  const int* ap_src = ei_ap;  const int* ap_dst = ei_ap + Eap;

  unsigned kpp0, kpp1, kaa0, kaa1;
  tf2x32(0u, 42u, 0u, 0u, kpp0, kpp1);
  tf2x32(0u, 42u, 0u, 1u, kaa0, kaa1);

  void* basep = nullptr;
  cudaGetSymbolAddress(&basep, g_arena);
  unsigned char* ar = (unsigned char*)basep;
  size_t off = 0;
  auto carve = [&](size_t bytes) -> unsigned char* {
    unsigned char* p = ar + off;
    off += (bytes + 255) & ~(size_t)255;
    return p;
  };
  float* AGGP  = (float*)carve((size_t)NPAP * HD * 4);
  float* AGGA  = (float*)carve((size_t)NAUT * HD * 4);
  float* AGGP2 = (float*)carve((size_t)NPAP * HD * 4);
  float* AGGA2 = (float*)carve((size_t)NAUT * HD * 4);
  float* HP0 = (float*)carve((size_t)NPAP * HD * 4);
  float* HP1 = (float*)carve((size_t)NPAP * HD * 4);
  float* HA0 = (float*)carve((size_t)NAUT * HD * 4);
  float* HA1 = (float*)carve((size_t)NAUT * HD * 4);
  float* UP = (float*)carve((size_t)NPAP * 256 * 4);
  float* VP = (float*)carve((size_t)NPAP * 256 * 4);
  float* UA = (float*)carve((size_t)NAUT * 256 * 4);
  float* VA = (float*)carve((size_t)NAUT * 256 * 4);
  int* CNT = (int*)carve(6 * 4096 * 4);
  int* CUR = (int*)carve(6 * 4096 * 4);
  int* OFF = (int*)carve(6 * 4097 * 4);
  int* P0 = (int*)carve((size_t)Epp * 4);
  int* P1 = (int*)carve((size_t)Epp * 4);
  int* P2 = (int*)carve((size_t)Eaa * 4);
  int* P3 = (int*)carve((size_t)Eaa * 4);
  int* P4 = (int*)carve((size_t)Epa * 4);
  int* P5 = (int*)carve((size_t)Eap * 4);
  int* SELPP = (int*)carve((size_t)NPAP * 5 * 4);
  int* SELAA = (int*)carve((size_t)NAUT * 5 * 4);

  EdgeJobs ej;
  const int* keys[6]  = {pp_dst, pp_src, aa_dst, aa_src, pa_dst, ap_dst};
  const int* parts[6] = {pp_src, pp_dst, aa_src, aa_dst, pa_src, ap_src};
  int ns[6] = {NPAP, NPAP, NAUT, NAUT, NAUT, NPAP};
  int Es[6] = {Epp, Epp, Eaa, Eaa, Epa, Eap};
  int packs[6] = {0, 1, 0, 1, 0, 0};
  int* outs[6] = {P0, P1, P2, P3, P4, P5};
  int run = 0;
  for (int r = 0; r < 6; r++) {
    ej.key[r] = keys[r]; ej.part[r] = parts[r];
    ej.off[r] = OFF + r * 4097;
    ej.cnt[r] = CNT + r * 4096; ej.cur[r] = CUR + r * 4096;
    ej.out[r] = outs[r]; ej.pack[r] = packs[r];
    ej.eStart[r] = run; run += Es[r];
  }
  ej.eStart[6] = run;
  cudaMemsetAsync(CNT, 0, 6 * 4096 * 4);
  count_all<<<(run / 8 + 255) / 256, 256>>>(ej, run);
  {
    ScanArgs sa;
    for (int r = 0; r < 6; r++) {
      sa.cnt[r] = CNT + r * 4096; sa.off[r] = OFF + r * 4097;
      sa.cur[r] = CUR + r * 4096; sa.n[r] = ns[r];
    }
    scan_kernel<<<6, 256>>>(sa);
  }
  fill_all<<<(run / 8 + 255) / 256, 256>>>(ej, run);

  auto makeG = [&](int csr, const float* H, float* o, const int* sel, int n) {
    GJob j; j.off = OFF + csr * 4097; j.part = outs[csr]; j.H = H; j.out = o;
    j.sel = sel; j.n = n; return j;
  };

  // ---- GNN1 ----
  {
    GJobs gj; gj.j[0] = makeG(0, x_p, AGGP, nullptr, NPAP);
    gj.j[1] = makeG(2, x_a, AGGA, nullptr, NAUT);
    gather_all<<<dim3((NPAP + 7) / 8, 2), 256>>>(gj);
  }
  {
    GemmJobs gs; gs.njobs = 2;
    gs.j[0] = {{x_p, AGGP, nullptr}, {Ws_p0, Wpp0, nullptr}, HP0, NPAP, 128, 2, 1, 0};
    gs.j[1] = {{x_a, AGGA, nullptr}, {Ws_a0, Waa0, nullptr}, HA0, NAUT, 128, 2, 1, 64};
    gemm_all<<<dim3(1, 96), 256>>>(gs);
  }
  {
    GJobs gj; gj.j[0] = makeG(0, HP0, AGGP, nullptr, NPAP);
    gj.j[1] = makeG(2, HA0, AGGA, nullptr, NAUT);
    gather_all<<<dim3((NPAP + 7) / 8, 2), 256>>>(gj);
  }
  {
    GemmJobs gs; gs.njobs = 2;
    gs.j[0] = {{HP0, AGGP, nullptr}, {Ws_p1, Wpp1, nullptr}, HP1, NPAP, 128, 2, 1, 0};
    gs.j[1] = {{HA0, AGGA, nullptr}, {Ws_a1, Waa1, nullptr}, HA1, NAUT, 128, 2, 1, 64};
    gemm_all<<<dim3(1, 96), 256>>>(gs);
  }
  // ---- edge-MLP projections (N=256) ----
  {
    GemmJobs gs; gs.njobs = 4;
    gs.j[0] = {{HP1, nullptr, nullptr}, {Wep1_pp, nullptr, nullptr}, UP, NPAP, 256, 1, 0, 0};
    gs.j[1] = {{HP1, nullptr, nullptr}, {Wep1_pp + 128 * 256, nullptr, nullptr}, VP, NPAP, 256, 1, 0, 64};
    gs.j[2] = {{HA1, nullptr, nullptr}, {Wep1_aa, nullptr, nullptr}, UA, NAUT, 256, 1, 0, 128};
    gs.j[3] = {{HA1, nullptr, nullptr}, {Wep1_aa + 128 * 256, nullptr, nullptr}, VA, NAUT, 256, 1, 0, 160};
    gemm_all<<<dim3(2, 192), 256>>>(gs);
  }
  // ---- prune (fused pp+aa, writes sel + w outputs) ----
  float* out_f = (float*)d_out;
  {
    PruneCfg cp = {OFF + 1 * 4097, P1, UP, VP, bep1_pp, Wep2_pp, bep2_pp,
                   4096, kpp0, kpp1, SELPP, out_f + 5};
    PruneCfg ca = {OFF + 3 * 4097, P3, UA, VA, bep1_aa, Wep2_aa, bep2_aa,
                   2048, kaa0, kaa1, SELAA, out_f + 5 + Epp};
    size_t smem = (4096 + 512) * sizeof(float) + CANDMAX * 8;
    prune_all<<<NPAP + NAUT, 256, smem>>>(cp, ca, NPAP);
  }
  // ---- GNN2 layer 0 ----
  {
    GJobs gj;
    gj.j[0] = makeG(0, x_p, AGGP, SELPP, NPAP);
    gj.j[1] = makeG(5, x_a, AGGP2, nullptr, NPAP);
    gj.j[2] = makeG(2, x_a, AGGA, SELAA, NAUT);
    gj.j[3] = makeG(4, x_p, AGGA2, nullptr, NAUT);
    gather_all<<<dim3((NPAP + 7) / 8, 4), 256>>>(gj);
  }
  {
    GemmJobs gs; gs.njobs = 2;
    gs.j[0] = {{x_p, AGGP, AGGP2}, {Ws_p0, Wpp0, Wap0}, HP0, NPAP, 128, 3, 1, 0};
    gs.j[1] = {{x_a, AGGA, AGGA2}, {Ws_a0, Waa0, Wpa0}, HA0, NAUT, 128, 3, 1, 64};
    gemm_all<<<dim3(1, 96), 256>>>(gs);
  }
  // ---- GNN2 layer 1 (node `index`) + classifier ----
  node_out_kernel<<<1, 128>>>(idxPtr, HP0, HA0,
                              OFF + 0 * 4097, P0, SELPP,
                              OFF + 5 * 4097, P5,
                              Ws_p1, Wpp1, Wap1, Wc, bc, out_f);
}